// round 9
// baseline (speedup 1.0000x reference)
#include <cuda_runtime.h>
#include <cuda_fp16.h>

#define B_    128
#define IN_   1024
#define OUT_  1024

constexpr float BETA    = 0.99f;
constexpr float THRESH  = 1.0f;
constexpr float RESETV  = 0.8f;
constexpr float INV_TAU = 0.05f;              // 1/20
constexpr float A_SC    = 0.005f / 128.0f;    // A / B

// ---- device scratch (static, allocation-free) ------------------------------
__device__ float g_Wt[IN_ * OUT_];            // Wt[k][o] = W[o][k]
__device__ int   g_sIdx[B_ * 256];            // spiking-k indices per batch (ordered)
__device__ int   g_sCnt[B_];
// Ipk slot layout: within each 64-i group g, i=(g*64+r) stored at uint2 slot
// g*64 + (r&31)*2 + (r>>5)  ->  (i, i+32) adjacent uint2 = one uint4.
__device__ uint2 g_Ipk[B_ * IN_];             // (p2, q2): e^{+dp/20}, e^{-dp/20}
__device__ uint2 g_Opk[B_ * OUT_ / 2];        // per o-pair (r2, -s2)

__device__ __forceinline__ __half2 u2h(unsigned u) { return *reinterpret_cast<__half2*>(&u); }
__device__ __forceinline__ unsigned h2u(__half2 h) { return *reinterpret_cast<unsigned*>(&h); }

// ---------------------------------------------------------------------------
// Front kernel: [0,256) transpose W -> Wt (64x64 float4 tiles);
//               [256,768) Ipack; [768,896) spike-index compaction.
// ---------------------------------------------------------------------------
__global__ __launch_bounds__(256) void k_front(
    const float* __restrict__ W,
    const float* __restrict__ spikes,
    const float* __restrict__ dpre)
{
    if (blockIdx.x < 256) {
        __shared__ float t[64][65];
        const int bx = (blockIdx.x & 15) * 64;   // k range
        const int by = (blockIdx.x >> 4) * 64;   // o range
        const int tx = threadIdx.x & 15;         // float4 col
        const int ty = threadIdx.x >> 4;         // 0..15

        #pragma unroll
        for (int r = 0; r < 4; r++) {
            int orow = ty + r * 16;
            float4 v = *reinterpret_cast<const float4*>(
                &W[(size_t)(by + orow) * IN_ + bx + tx * 4]);
            t[orow][tx * 4 + 0] = v.x;
            t[orow][tx * 4 + 1] = v.y;
            t[orow][tx * 4 + 2] = v.z;
            t[orow][tx * 4 + 3] = v.w;
        }
        __syncthreads();
        #pragma unroll
        for (int r = 0; r < 4; r++) {
            int krow = ty + r * 16;
            float4 v = make_float4(t[tx * 4 + 0][krow], t[tx * 4 + 1][krow],
                                   t[tx * 4 + 2][krow], t[tx * 4 + 3][krow]);
            *reinterpret_cast<float4*>(
                &g_Wt[(size_t)(bx + krow) * OUT_ + by + tx * 4]) = v;
        }
    } else if (blockIdx.x < 768) {
        int idx = (blockIdx.x - 256) * 256 + threadIdx.x;  // b*IN_ + i
        float dp = (spikes[idx] > 0.0f) ? 0.0f : dpre[idx] + 1.0f;
        uint2 u;
        u.x = h2u(__float2half2_rn(__expf(dp * INV_TAU)));   // p pair
        u.y = h2u(__float2half2_rn(__expf(-dp * INV_TAU)));  // q pair
        int i = idx & (IN_ - 1);
        int b = idx >> 10;
        int g = i >> 6, r = i & 63;
        int slot = (g << 6) + ((r & 31) << 1) + (r >> 5);
        g_Ipk[b * IN_ + slot] = u;
    } else {
        // spike-index compaction for batch b (deterministic, order-preserving)
        __shared__ int wsum[8];
        __shared__ int wbase[8];
        const int b = blockIdx.x - 768;
        const int tid = threadIdx.x;
        const int lane = tid & 31, wid = tid >> 5;

        float4 sp = reinterpret_cast<const float4*>(spikes)[b * 256 + tid];
        int f0 = sp.x > 0.0f, f1 = sp.y > 0.0f, f2 = sp.z > 0.0f, f3 = sp.w > 0.0f;
        int c = f0 + f1 + f2 + f3;

        int s = c;                                 // inclusive warp scan
        #pragma unroll
        for (int d = 1; d < 32; d <<= 1) {
            int v = __shfl_up_sync(0xFFFFFFFFu, s, d);
            if (lane >= d) s += v;
        }
        if (lane == 31) wsum[wid] = s;
        __syncthreads();
        if (tid == 0) {
            int acc = 0;
            #pragma unroll
            for (int w = 0; w < 8; w++) { wbase[w] = acc; acc += wsum[w]; }
            g_sCnt[b] = acc;
        }
        __syncthreads();

        int base = wbase[wid] + (s - c);           // exclusive offset
        int k0 = tid * 4;
        int* dst = &g_sIdx[b * 256];
        if (f0) dst[base++] = k0;
        if (f1) dst[base++] = k0 + 1;
        if (f2) dst[base++] = k0 + 2;
        if (f3) dst[base  ] = k0 + 3;
    }
}

// ---------------------------------------------------------------------------
// Fused sparse matmul + LIF + Opack.
// grid (4 o-chunks of 256, 128 b). 256 threads, thread = one o.
// ---------------------------------------------------------------------------
__global__ __launch_bounds__(256) void k_mm_lif(
    const float* __restrict__ membrane, const float* __restrict__ dfire,
    float* __restrict__ out_spike, float* __restrict__ out_mem)
{
    __shared__ int sk[256];
    const int tid = threadIdx.x;
    const int b = blockIdx.y;
    const int o = blockIdx.x * 256 + tid;

    const int cnt = g_sCnt[b];
    if (tid < cnt) sk[tid] = g_sIdx[b * 256 + tid];
    __syncthreads();

    float a0 = 0.f, a1 = 0.f, a2 = 0.f, a3 = 0.f;
    int j = 0;
    for (; j + 4 <= cnt; j += 4) {
        int k0 = sk[j], k1 = sk[j + 1], k2 = sk[j + 2], k3 = sk[j + 3];
        a0 += g_Wt[(size_t)k0 * OUT_ + o];
        a1 += g_Wt[(size_t)k1 * OUT_ + o];
        a2 += g_Wt[(size_t)k2 * OUT_ + o];
        a3 += g_Wt[(size_t)k3 * OUT_ + o];
    }
    for (; j < cnt; j++)
        a0 += g_Wt[(size_t)sk[j] * OUT_ + o];
    float wsum = (a0 + a1) + (a2 + a3);

    const int base = b * OUT_ + o;
    float m = membrane[base] * BETA + wsum;
    float sp = (m > THRESH) ? 1.0f : 0.0f;
    if (sp > 0.f) m -= RESETV;
    out_spike[base] = sp;
    out_mem[base]   = m;

    float df = (sp > 0.f) ? 0.0f : dfire[base] + 1.0f;
    float r  = __expf(-df * INV_TAU);
    float ns = -__expf(df * INV_TAU);
    float r1  = __shfl_xor_sync(0xFFFFFFFFu, r, 1);
    float ns1 = __shfl_xor_sync(0xFFFFFFFFu, ns, 1);
    if (!(o & 1)) {
        uint2 u;
        u.x = h2u(__floats2half2_rn(r, r1));    // (r_o, r_o+1)
        u.y = h2u(__floats2half2_rn(ns, ns1));  // (-s_o, -s_o+1)
        g_Opk[base >> 1] = u;
    }
}

// ---------------------------------------------------------------------------
// STDP via product-vs-1 test (exact at dp==df):
//   t1 = p*r < 1  <=> df > dp : contribute +t1
//   t2 = q*(-s) > -1 <=> df < dp : contribute t2
// Tile 128i x 16o, grid (64 o-blk, 8 i-blk) = 512 blocks, 128 threads.
// Thread: 4 i (two interleaved uint4) x 4 o (one uint4 broadcast);
// b-loop prefetched one iteration ahead.
// ---------------------------------------------------------------------------
__global__ __launch_bounds__(128) void k_stdp(
    const float* __restrict__ W, float* __restrict__ outW)
{
    __shared__ uint4 sI[16][64];   // 16 KB: (p,q) for i = jj*32 + tx, jj=0..3
    __shared__ uint4 sO[16][4];    //  1 KB: o-quads

    const int tid = threadIdx.x;
    const int tx = tid & 31;       // lane
    const int wp = tid >> 5;       // warp (0..3) -> o-quad
    const int oBase = blockIdx.x * 16;
    const int iBase = blockIdx.y * 128;

    const __half2 ONE  = __float2half2_rn(1.0f);
    const __half2 NEG1 = __float2half2_rn(-1.0f);

    float accf[4][2][2];           // [i-sub][o-pair][lo/hi]
    #pragma unroll
    for (int j = 0; j < 4; j++)
        #pragma unroll
        for (int c = 0; c < 2; c++) { accf[j][c][0] = 0.f; accf[j][c][1] = 0.f; }

    const uint4* Ipk4 = reinterpret_cast<const uint4*>(g_Ipk);
    const uint4* Opk4 = reinterpret_cast<const uint4*>(g_Opk);

    for (int cb = 0; cb < 8; cb++) {           // 8 chunks of 16 batches
        // sI: 16 b x 64 uint4 = 1024; 8 per thread, coalesced LDG.128
        #pragma unroll
        for (int t = tid; t < 1024; t += 128) {
            int b = t >> 6, j = t & 63;
            sI[b][j] = Ipk4[((cb * 16 + b) * IN_ + iBase) / 2 + j];
        }
        // sO: 16 b x 4 uint4 = 64
        if (tid < 64) {
            int b = tid >> 2, j = tid & 3;
            sO[b][j] = Opk4[(cb * 16 + b) * (OUT_ / 4) + (oBase >> 2) + j];
        }
        __syncthreads();

        __half2 acch[4][2];
        #pragma unroll
        for (int j = 0; j < 4; j++) {
            acch[j][0] = __float2half2_rn(0.f);
            acch[j][1] = __float2half2_rn(0.f);
        }

        // software-pipelined: prefetch b+1 while computing b
        uint4 iv0 = sI[0][tx];
        uint4 iv1 = sI[0][32 + tx];
        uint4 ov  = sO[0][wp];
        #pragma unroll
        for (int b = 0; b < 16; b++) {
            uint4 iv0n, iv1n, ovn;
            if (b < 15) {
                iv0n = sI[b + 1][tx];          // LDS.128 conflict-free
                iv1n = sI[b + 1][32 + tx];
                ovn  = sO[b + 1][wp];          // LDS.128 broadcast
            }
            __half2 pq[4][2] = {{u2h(iv0.x), u2h(iv0.y)}, {u2h(iv0.z), u2h(iv0.w)},
                                {u2h(iv1.x), u2h(iv1.y)}, {u2h(iv1.z), u2h(iv1.w)}};
            __half2 rs[2][2] = {{u2h(ov.x), u2h(ov.y)}, {u2h(ov.z), u2h(ov.w)}};
            #pragma unroll
            for (int j = 0; j < 4; j++) {      // i-sub
                #pragma unroll
                for (int c = 0; c < 2; c++) {  // o-pair
                    __half2 t1 = __hmul2(pq[j][0], rs[c][0]);
                    __half2 t2 = __hmul2(pq[j][1], rs[c][1]);
                    __half2 m1 = __hlt2(t1, ONE);
                    __half2 m2 = __hgt2(t2, NEG1);
                    acch[j][c] = __hfma2(m1, t1, acch[j][c]);
                    acch[j][c] = __hfma2(m2, t2, acch[j][c]);
                }
            }
            iv0 = iv0n; iv1 = iv1n; ov = ovn;
        }

        #pragma unroll
        for (int j = 0; j < 4; j++)
            #pragma unroll
            for (int c = 0; c < 2; c++) {
                accf[j][c][0] += __low2float(acch[j][c]);
                accf[j][c][1] += __high2float(acch[j][c]);
            }
        __syncthreads();
    }

    // epilogue: i-subs at {tx, tx+32, tx+64, tx+96}; 128B coalesced stores
    #pragma unroll
    for (int j = 0; j < 4; j++) {
        const int i = iBase + j * 32 + tx;
        #pragma unroll
        for (int c = 0; c < 2; c++) {
            #pragma unroll
            for (int h = 0; h < 2; h++) {
                int o = oBase + wp * 4 + c * 2 + h;
                size_t off = (size_t)o * IN_ + i;
                outW[off] = W[off] + accf[j][c][h] * A_SC;
            }
        }
    }
}

// ---------------------------------------------------------------------------
extern "C" void kernel_launch(void* const* d_in, const int* in_sizes, int n_in,
                              void* d_out, int out_size)
{
    const float* spikes   = (const float*)d_in[0];
    const float* W        = (const float*)d_in[1];
    const float* membrane = (const float*)d_in[2];
    const float* dpre     = (const float*)d_in[3];
    const float* dfire    = (const float*)d_in[4];

    float* out       = (float*)d_out;
    float* out_spike = out;                                   // (B, OUT)
    float* out_W     = out + B_ * OUT_;                       // (OUT, IN)
    float* out_mem   = out + B_ * OUT_ + (size_t)OUT_ * IN_;  // (B, OUT)

    k_front<<<896, 256>>>(W, spikes, dpre);
    k_mm_lif<<<dim3(4, 128), 256>>>(membrane, dfire, out_spike, out_mem);
    k_stdp<<<dim3(64, 8), 128>>>(W, out_W);
}

// round 10
// speedup vs baseline: 1.1088x; 1.1088x over previous
#include <cuda_runtime.h>
#include <cuda_fp16.h>

#define B_    128
#define IN_   1024
#define OUT_  1024

constexpr float BETA    = 0.99f;
constexpr float THRESH  = 1.0f;
constexpr float RESETV  = 0.8f;
constexpr float INV_TAU = 0.05f;              // 1/20
constexpr float A_SC    = 0.005f / 128.0f;    // A / B

// ---- device scratch (static, allocation-free) ------------------------------
__device__ float g_Wt[IN_ * OUT_];            // Wt[k][o] = W[o][k]
__device__ int   g_sIdx[B_ * 256];            // spiking-k indices per batch (ordered)
__device__ int   g_sCnt[B_];
// Ipk slot layout: within each 64-i group g, i=(g*64+r) stored at uint2 slot
// g*64 + (r&31)*2 + (r>>5)  ->  (i, i+32) adjacent uint2 = one uint4.
__device__ uint2 g_Ipk[B_ * IN_];             // (p2, q2): e^{+dp/20}, e^{-dp/20}
__device__ uint2 g_Opk[B_ * OUT_ / 2];        // per o-pair (r2, -s2)

__device__ __forceinline__ __half2 u2h(unsigned u) { return *reinterpret_cast<__half2*>(&u); }
__device__ __forceinline__ unsigned h2u(__half2 h) { return *reinterpret_cast<unsigned*>(&h); }

// ---------------------------------------------------------------------------
// Front kernel (R8 version): [0,1024) transpose W -> Wt (32x32 tiles);
// [1024,1536) Ipack; [1536,1664) spike-index compaction.
// ---------------------------------------------------------------------------
__global__ __launch_bounds__(256) void k_front(
    const float* __restrict__ W,
    const float* __restrict__ spikes,
    const float* __restrict__ dpre)
{
    if (blockIdx.x < 1024) {
        __shared__ float t[32][33];
        const int bx = (blockIdx.x & 31) * 32;   // k range
        const int by = (blockIdx.x >> 5) * 32;   // o range
        const int tx = threadIdx.x & 31;
        const int ty = threadIdx.x >> 5;         // 0..7
        #pragma unroll
        for (int i = 0; i < 32; i += 8)
            t[ty + i][tx] = W[(size_t)(by + ty + i) * IN_ + bx + tx];
        __syncthreads();
        #pragma unroll
        for (int i = 0; i < 32; i += 8)
            g_Wt[(size_t)(bx + ty + i) * OUT_ + by + tx] = t[tx][ty + i];
    } else if (blockIdx.x < 1536) {
        int idx = (blockIdx.x - 1024) * 256 + threadIdx.x;  // b*IN_ + i
        float dp = (spikes[idx] > 0.0f) ? 0.0f : dpre[idx] + 1.0f;
        uint2 u;
        u.x = h2u(__float2half2_rn(__expf(dp * INV_TAU)));   // p pair
        u.y = h2u(__float2half2_rn(__expf(-dp * INV_TAU)));  // q pair
        int i = idx & (IN_ - 1);
        int b = idx >> 10;
        int g = i >> 6, r = i & 63;
        int slot = (g << 6) + ((r & 31) << 1) + (r >> 5);
        g_Ipk[b * IN_ + slot] = u;
    } else {
        // spike-index compaction for batch b (deterministic, order-preserving)
        __shared__ int wsum[8];
        __shared__ int wbase[8];
        const int b = blockIdx.x - 1536;
        const int tid = threadIdx.x;
        const int lane = tid & 31, wid = tid >> 5;

        float4 sp = reinterpret_cast<const float4*>(spikes)[b * 256 + tid];
        int f0 = sp.x > 0.0f, f1 = sp.y > 0.0f, f2 = sp.z > 0.0f, f3 = sp.w > 0.0f;
        int c = f0 + f1 + f2 + f3;

        int s = c;                                 // inclusive warp scan
        #pragma unroll
        for (int d = 1; d < 32; d <<= 1) {
            int v = __shfl_up_sync(0xFFFFFFFFu, s, d);
            if (lane >= d) s += v;
        }
        if (lane == 31) wsum[wid] = s;
        __syncthreads();
        if (tid == 0) {
            int acc = 0;
            #pragma unroll
            for (int w = 0; w < 8; w++) { wbase[w] = acc; acc += wsum[w]; }
            g_sCnt[b] = acc;
        }
        __syncthreads();

        int base = wbase[wid] + (s - c);           // exclusive offset
        int k0 = tid * 4;
        int* dst = &g_sIdx[b * 256];
        if (f0) dst[base++] = k0;
        if (f1) dst[base++] = k0 + 1;
        if (f2) dst[base++] = k0 + 2;
        if (f3) dst[base  ] = k0 + 3;
    }
}

// ---------------------------------------------------------------------------
// Fused sparse matmul + LIF + Opack. (unchanged from R8)
// grid (4 o-chunks of 256, 128 b). 256 threads, thread = one o.
// ---------------------------------------------------------------------------
__global__ __launch_bounds__(256) void k_mm_lif(
    const float* __restrict__ membrane, const float* __restrict__ dfire,
    float* __restrict__ out_spike, float* __restrict__ out_mem)
{
    __shared__ int sk[256];
    const int tid = threadIdx.x;
    const int b = blockIdx.y;
    const int o = blockIdx.x * 256 + tid;

    const int cnt = g_sCnt[b];
    if (tid < cnt) sk[tid] = g_sIdx[b * 256 + tid];
    __syncthreads();

    float a0 = 0.f, a1 = 0.f, a2 = 0.f, a3 = 0.f;
    int j = 0;
    for (; j + 4 <= cnt; j += 4) {
        int k0 = sk[j], k1 = sk[j + 1], k2 = sk[j + 2], k3 = sk[j + 3];
        a0 += g_Wt[(size_t)k0 * OUT_ + o];
        a1 += g_Wt[(size_t)k1 * OUT_ + o];
        a2 += g_Wt[(size_t)k2 * OUT_ + o];
        a3 += g_Wt[(size_t)k3 * OUT_ + o];
    }
    for (; j < cnt; j++)
        a0 += g_Wt[(size_t)sk[j] * OUT_ + o];
    float wsum = (a0 + a1) + (a2 + a3);

    const int base = b * OUT_ + o;
    float m = membrane[base] * BETA + wsum;
    float sp = (m > THRESH) ? 1.0f : 0.0f;
    if (sp > 0.f) m -= RESETV;
    out_spike[base] = sp;
    out_mem[base]   = m;

    float df = (sp > 0.f) ? 0.0f : dfire[base] + 1.0f;
    float r  = __expf(-df * INV_TAU);
    float ns = -__expf(df * INV_TAU);
    float r1  = __shfl_xor_sync(0xFFFFFFFFu, r, 1);
    float ns1 = __shfl_xor_sync(0xFFFFFFFFu, ns, 1);
    if (!(o & 1)) {
        uint2 u;
        u.x = h2u(__floats2half2_rn(r, r1));    // (r_o, r_o+1)
        u.y = h2u(__floats2half2_rn(ns, ns1));  // (-s_o, -s_o+1)
        g_Opk[base >> 1] = u;
    }
}

// ---------------------------------------------------------------------------
// STDP via product-vs-1 test (exact at dp==df):
//   t1 = p*r < 1  <=> df > dp : contribute +t1
//   t2 = q*(-s) > -1 <=> df < dp : contribute t2
// Tile 64i x 16o, grid (64 o-blk, 16 i-blk) = 1024 blocks, 128 threads.
// DOUBLE-BUFFERED chunk staging: while computing chunk cb from buf (cb&1),
// the LDG->STS for chunk cb+1 lands in the other buffer; one sync per chunk
// (BAR.SYNC drains pending STS). Inner b-loop register-prefetched as in R8.
// ---------------------------------------------------------------------------
__global__ __launch_bounds__(128) void k_stdp(
    const float* __restrict__ W, float* __restrict__ outW)
{
    __shared__ uint4 sI[2][16][32];   // 2 x 8 KB
    __shared__ uint4 sO[2][16][4];    // 2 x 1 KB

    const int tid = threadIdx.x;
    const int tx = tid & 31;       // lane -> i (and i+32)
    const int wp = tid >> 5;       // warp (0..3) -> o-quad
    const int oBase = blockIdx.x * 16;
    const int iBase = blockIdx.y * 64;

    const __half2 ONE  = __float2half2_rn(1.0f);
    const __half2 NEG1 = __float2half2_rn(-1.0f);

    float accf[2][2][2];           // [i-half][o-pair][lo/hi]
    #pragma unroll
    for (int j = 0; j < 2; j++)
        #pragma unroll
        for (int c = 0; c < 2; c++) { accf[j][c][0] = 0.f; accf[j][c][1] = 0.f; }

    const uint4* Ipk4 = reinterpret_cast<const uint4*>(g_Ipk);
    const uint4* Opk4 = reinterpret_cast<const uint4*>(g_Opk);

    // indices for this thread's staging slice (fixed across chunks)
    const int sb = tid >> 5;               // sI batch-sub (strided +4 below)
    const int sj = tid & 31;               // sI column
    const int ob = tid >> 2;               // sO batch (tid<64)
    const int oj = tid & 3;                // sO column

    // stage chunk 0 into buffer 0
    #pragma unroll
    for (int r = 0; r < 4; r++)
        sI[0][sb + r * 4][sj] = Ipk4[((sb + r * 4) * IN_ + iBase) / 2 + sj];
    if (tid < 64)
        sO[0][ob][oj] = Opk4[ob * (OUT_ / 4) + (oBase >> 2) + oj];
    __syncthreads();

    for (int cb = 0; cb < 8; cb++) {           // 8 chunks of 16 batches
        const int cur = cb & 1;

        // kick off next chunk's staging into the other buffer (overlaps math)
        if (cb < 7) {
            const int nb = (cb + 1) * 16;
            #pragma unroll
            for (int r = 0; r < 4; r++)
                sI[cur ^ 1][sb + r * 4][sj] =
                    Ipk4[((nb + sb + r * 4) * IN_ + iBase) / 2 + sj];
            if (tid < 64)
                sO[cur ^ 1][ob][oj] =
                    Opk4[(nb + ob) * (OUT_ / 4) + (oBase >> 2) + oj];
        }

        __half2 acch[2][2];
        #pragma unroll
        for (int j = 0; j < 2; j++) {
            acch[j][0] = __float2half2_rn(0.f);
            acch[j][1] = __float2half2_rn(0.f);
        }

        // software-pipelined: prefetch b+1 while computing b
        uint4 iv = sI[cur][0][tx];
        uint4 ov = sO[cur][0][wp];
        #pragma unroll
        for (int b = 0; b < 16; b++) {
            uint4 ivn, ovn;
            if (b < 15) {
                ivn = sI[cur][b + 1][tx];      // LDS.128 conflict-free
                ovn = sO[cur][b + 1][wp];      // LDS.128 broadcast
            }
            __half2 pq[2][2] = {{u2h(iv.x), u2h(iv.y)}, {u2h(iv.z), u2h(iv.w)}};
            __half2 rs[2][2] = {{u2h(ov.x), u2h(ov.y)}, {u2h(ov.z), u2h(ov.w)}};
            #pragma unroll
            for (int j = 0; j < 2; j++) {      // i-half
                #pragma unroll
                for (int c = 0; c < 2; c++) {  // o-pair
                    __half2 t1 = __hmul2(pq[j][0], rs[c][0]);
                    __half2 t2 = __hmul2(pq[j][1], rs[c][1]);
                    __half2 m1 = __hlt2(t1, ONE);
                    __half2 m2 = __hgt2(t2, NEG1);
                    acch[j][c] = __hfma2(m1, t1, acch[j][c]);
                    acch[j][c] = __hfma2(m2, t2, acch[j][c]);
                }
            }
            iv = ivn; ov = ovn;
        }

        #pragma unroll
        for (int j = 0; j < 2; j++)
            #pragma unroll
            for (int c = 0; c < 2; c++) {
                accf[j][c][0] += __low2float(acch[j][c]);
                accf[j][c][1] += __high2float(acch[j][c]);
            }
        __syncthreads();   // drains next-chunk STS; releases cur for reuse
    }

    // epilogue: lanes along i -> 128B coalesced stores
    #pragma unroll
    for (int j = 0; j < 2; j++) {
        const int i = iBase + j * 32 + tx;
        #pragma unroll
        for (int c = 0; c < 2; c++) {
            #pragma unroll
            for (int h = 0; h < 2; h++) {
                int o = oBase + wp * 4 + c * 2 + h;
                size_t off = (size_t)o * IN_ + i;
                outW[off] = W[off] + accf[j][c][h] * A_SC;
            }
        }
    }
}

// ---------------------------------------------------------------------------
extern "C" void kernel_launch(void* const* d_in, const int* in_sizes, int n_in,
                              void* d_out, int out_size)
{
    const float* spikes   = (const float*)d_in[0];
    const float* W        = (const float*)d_in[1];
    const float* membrane = (const float*)d_in[2];
    const float* dpre     = (const float*)d_in[3];
    const float* dfire    = (const float*)d_in[4];

    float* out       = (float*)d_out;
    float* out_spike = out;                                   // (B, OUT)
    float* out_W     = out + B_ * OUT_;                       // (OUT, IN)
    float* out_mem   = out + B_ * OUT_ + (size_t)OUT_ * IN_;  // (B, OUT)

    k_front<<<1664, 256>>>(W, spikes, dpre);
    k_mm_lif<<<dim3(4, 128), 256>>>(membrane, dfire, out_spike, out_mem);
    k_stdp<<<dim3(64, 16), 128>>>(W, out_W);
}

// round 11
// speedup vs baseline: 1.1174x; 1.0077x over previous
#include <cuda_runtime.h>
#include <cuda_fp16.h>

#define B_    128
#define IN_   1024
#define OUT_  1024

constexpr float BETA    = 0.99f;
constexpr float THRESH  = 1.0f;
constexpr float RESETV  = 0.8f;
constexpr float INV_TAU = 0.05f;              // 1/20
constexpr float A_SC    = 0.005f / 128.0f;    // A / B

// ---- device scratch (static, allocation-free) ------------------------------
__device__ float g_Wt[IN_ * OUT_];            // Wt[k][o] = W[o][k]
__device__ int   g_sIdx[B_ * 256];            // spiking-k indices per batch (ordered)
__device__ int   g_sCnt[B_];
// Ipk slot layout: within each 64-i group g, i=(g*64+r) stored at uint2 slot
// g*64 + (r&31)*2 + (r>>5)  ->  (i, i+32) adjacent uint2 = one uint4.
__device__ uint2 g_Ipk[B_ * IN_];             // (p2, q2): e^{+dp/20}, e^{-dp/20}
__device__ uint2 g_Opk[B_ * OUT_ / 2];        // per o-pair (r2, -s2)

__device__ __forceinline__ __half2 u2h(unsigned u) { return *reinterpret_cast<__half2*>(&u); }
__device__ __forceinline__ unsigned h2u(__half2 h) { return *reinterpret_cast<unsigned*>(&h); }

// ---------------------------------------------------------------------------
// Front kernel: [0,1024) transpose W -> Wt (32x32 tiles, float4 I/O);
// [1024,1536) Ipack; [1536,1664) spike-index compaction.
// ---------------------------------------------------------------------------
__global__ __launch_bounds__(256) void k_front(
    const float* __restrict__ W,
    const float* __restrict__ spikes,
    const float* __restrict__ dpre)
{
    if (blockIdx.x < 1024) {
        __shared__ float t[32][33];          // [o-row][k-col], 33 -> conflict-free
        const int bx = (blockIdx.x & 31) * 32;   // k range
        const int by = (blockIdx.x >> 5) * 32;   // o range
        const int c8 = threadIdx.x & 7;          // float4 column
        const int rw = threadIdx.x >> 3;         // row 0..31

        float4 v = *reinterpret_cast<const float4*>(
            &W[(size_t)(by + rw) * IN_ + bx + c8 * 4]);
        t[rw][c8 * 4 + 0] = v.x;
        t[rw][c8 * 4 + 1] = v.y;
        t[rw][c8 * 4 + 2] = v.z;
        t[rw][c8 * 4 + 3] = v.w;
        __syncthreads();

        float4 o4 = make_float4(t[c8 * 4 + 0][rw], t[c8 * 4 + 1][rw],
                                t[c8 * 4 + 2][rw], t[c8 * 4 + 3][rw]);
        *reinterpret_cast<float4*>(
            &g_Wt[(size_t)(bx + rw) * OUT_ + by + c8 * 4]) = o4;
    } else if (blockIdx.x < 1536) {
        int idx = (blockIdx.x - 1024) * 256 + threadIdx.x;  // b*IN_ + i
        float dp = (spikes[idx] > 0.0f) ? 0.0f : dpre[idx] + 1.0f;
        uint2 u;
        u.x = h2u(__float2half2_rn(__expf(dp * INV_TAU)));   // p pair
        u.y = h2u(__float2half2_rn(__expf(-dp * INV_TAU)));  // q pair
        int i = idx & (IN_ - 1);
        int b = idx >> 10;
        int g = i >> 6, r = i & 63;
        int slot = (g << 6) + ((r & 31) << 1) + (r >> 5);
        g_Ipk[b * IN_ + slot] = u;
    } else {
        // spike-index compaction for batch b (deterministic, order-preserving)
        __shared__ int wsum[8];
        __shared__ int wbase[8];
        const int b = blockIdx.x - 1536;
        const int tid = threadIdx.x;
        const int lane = tid & 31, wid = tid >> 5;

        float4 sp = reinterpret_cast<const float4*>(spikes)[b * 256 + tid];
        int f0 = sp.x > 0.0f, f1 = sp.y > 0.0f, f2 = sp.z > 0.0f, f3 = sp.w > 0.0f;
        int c = f0 + f1 + f2 + f3;

        int s = c;                                 // inclusive warp scan
        #pragma unroll
        for (int d = 1; d < 32; d <<= 1) {
            int v = __shfl_up_sync(0xFFFFFFFFu, s, d);
            if (lane >= d) s += v;
        }
        if (lane == 31) wsum[wid] = s;
        __syncthreads();
        if (tid == 0) {
            int acc = 0;
            #pragma unroll
            for (int w = 0; w < 8; w++) { wbase[w] = acc; acc += wsum[w]; }
            g_sCnt[b] = acc;
        }
        __syncthreads();

        int base = wbase[wid] + (s - c);           // exclusive offset
        int k0 = tid * 4;
        int* dst = &g_sIdx[b * 256];
        if (f0) dst[base++] = k0;
        if (f1) dst[base++] = k0 + 1;
        if (f2) dst[base++] = k0 + 2;
        if (f3) dst[base  ] = k0 + 3;
    }
}

// ---------------------------------------------------------------------------
// Fused sparse matmul + LIF + Opack.
// grid (2 o-chunks of 512, 128 b). 256 threads, thread = one o-PAIR (float2).
// Wt L2 traffic halved vs o-chunk-256 (26MB); Opk pair written directly.
// ---------------------------------------------------------------------------
__global__ __launch_bounds__(256) void k_mm_lif(
    const float* __restrict__ membrane, const float* __restrict__ dfire,
    float* __restrict__ out_spike, float* __restrict__ out_mem)
{
    __shared__ int sk[256];
    const int tid = threadIdx.x;
    const int b = blockIdx.y;
    const int o0 = blockIdx.x * 512 + tid * 2;    // even o

    const int cnt = g_sCnt[b];
    if (tid < cnt) sk[tid] = g_sIdx[b * 256 + tid];
    __syncthreads();

    float2 a0 = make_float2(0.f, 0.f), a1 = make_float2(0.f, 0.f);
    float2 a2 = make_float2(0.f, 0.f), a3 = make_float2(0.f, 0.f);
    int j = 0;
    for (; j + 4 <= cnt; j += 4) {
        int k0 = sk[j], k1 = sk[j + 1], k2 = sk[j + 2], k3 = sk[j + 3];
        float2 w0 = *reinterpret_cast<const float2*>(&g_Wt[(size_t)k0 * OUT_ + o0]);
        float2 w1 = *reinterpret_cast<const float2*>(&g_Wt[(size_t)k1 * OUT_ + o0]);
        float2 w2 = *reinterpret_cast<const float2*>(&g_Wt[(size_t)k2 * OUT_ + o0]);
        float2 w3 = *reinterpret_cast<const float2*>(&g_Wt[(size_t)k3 * OUT_ + o0]);
        a0.x += w0.x; a0.y += w0.y;
        a1.x += w1.x; a1.y += w1.y;
        a2.x += w2.x; a2.y += w2.y;
        a3.x += w3.x; a3.y += w3.y;
    }
    for (; j < cnt; j++) {
        float2 w = *reinterpret_cast<const float2*>(&g_Wt[(size_t)sk[j] * OUT_ + o0]);
        a0.x += w.x; a0.y += w.y;
    }
    float w0 = (a0.x + a1.x) + (a2.x + a3.x);
    float w1 = (a0.y + a1.y) + (a2.y + a3.y);

    const int base = b * OUT_ + o0;
    float2 mem = *reinterpret_cast<const float2*>(&membrane[base]);
    float2 dfr = *reinterpret_cast<const float2*>(&dfire[base]);

    float m0 = mem.x * BETA + w0, m1 = mem.y * BETA + w1;
    float s0 = (m0 > THRESH) ? 1.0f : 0.0f;
    float s1 = (m1 > THRESH) ? 1.0f : 0.0f;
    if (s0 > 0.f) m0 -= RESETV;
    if (s1 > 0.f) m1 -= RESETV;

    *reinterpret_cast<float2*>(&out_spike[base]) = make_float2(s0, s1);
    *reinterpret_cast<float2*>(&out_mem[base])   = make_float2(m0, m1);

    float df0 = (s0 > 0.f) ? 0.0f : dfr.x + 1.0f;
    float df1 = (s1 > 0.f) ? 0.0f : dfr.y + 1.0f;
    uint2 u;
    u.x = h2u(__floats2half2_rn(__expf(-df0 * INV_TAU), __expf(-df1 * INV_TAU)));  // r
    u.y = h2u(__floats2half2_rn(-__expf(df0 * INV_TAU), -__expf(df1 * INV_TAU))); // -s
    g_Opk[base >> 1] = u;
}

// ---------------------------------------------------------------------------
// STDP via product-vs-1 test (exact at dp==df) — byte-identical to R8 best:
//   t1 = p*r < 1  <=> df > dp : contribute +t1
//   t2 = q*(-s) > -1 <=> df < dp : contribute t2
// Tile 64i x 16o, grid (64 o-blk, 16 i-blk) = 1024 blocks, 128 threads.
// Inner b-loop register-prefetched one iteration ahead.
// ---------------------------------------------------------------------------
__global__ __launch_bounds__(128) void k_stdp(
    const float* __restrict__ W, float* __restrict__ outW)
{
    __shared__ uint4 sI[16][32];   // 8 KB: (p,q) for i=j and i=j+32
    __shared__ uint4 sO[16][4];    // 1 KB: o-quads

    const int tid = threadIdx.x;
    const int tx = tid & 31;       // lane -> i (and i+32)
    const int wp = tid >> 5;       // warp (0..3) -> o-quad
    const int oBase = blockIdx.x * 16;
    const int iBase = blockIdx.y * 64;

    const __half2 ONE  = __float2half2_rn(1.0f);
    const __half2 NEG1 = __float2half2_rn(-1.0f);

    float accf[2][2][2];           // [i-half][o-pair][lo/hi]
    #pragma unroll
    for (int j = 0; j < 2; j++)
        #pragma unroll
        for (int c = 0; c < 2; c++) { accf[j][c][0] = 0.f; accf[j][c][1] = 0.f; }

    const uint4* Ipk4 = reinterpret_cast<const uint4*>(g_Ipk);
    const uint4* Opk4 = reinterpret_cast<const uint4*>(g_Opk);

    for (int cb = 0; cb < 8; cb++) {           // 8 chunks of 16 batches
        // sI: 16 b x 32 uint4 = 512; 4 per thread, coalesced LDG.128
        #pragma unroll
        for (int t = tid; t < 512; t += 128) {
            int b = t >> 5, j = t & 31;
            sI[b][j] = Ipk4[((cb * 16 + b) * IN_ + iBase) / 2 + j];
        }
        // sO: 16 b x 4 uint4 = 64
        if (tid < 64) {
            int b = tid >> 2, j = tid & 3;
            sO[b][j] = Opk4[(cb * 16 + b) * (OUT_ / 4) + (oBase >> 2) + j];
        }
        __syncthreads();

        __half2 acch[2][2];
        #pragma unroll
        for (int j = 0; j < 2; j++) {
            acch[j][0] = __float2half2_rn(0.f);
            acch[j][1] = __float2half2_rn(0.f);
        }

        // software-pipelined: prefetch b+1 while computing b
        uint4 iv = sI[0][tx];
        uint4 ov = sO[0][wp];
        #pragma unroll
        for (int b = 0; b < 16; b++) {
            uint4 ivn, ovn;
            if (b < 15) {
                ivn = sI[b + 1][tx];           // LDS.128 conflict-free
                ovn = sO[b + 1][wp];           // LDS.128 broadcast
            }
            __half2 pq[2][2] = {{u2h(iv.x), u2h(iv.y)}, {u2h(iv.z), u2h(iv.w)}};
            __half2 rs[2][2] = {{u2h(ov.x), u2h(ov.y)}, {u2h(ov.z), u2h(ov.w)}};
            #pragma unroll
            for (int j = 0; j < 2; j++) {      // i-half
                #pragma unroll
                for (int c = 0; c < 2; c++) {  // o-pair
                    __half2 t1 = __hmul2(pq[j][0], rs[c][0]);
                    __half2 t2 = __hmul2(pq[j][1], rs[c][1]);
                    __half2 m1 = __hlt2(t1, ONE);
                    __half2 m2 = __hgt2(t2, NEG1);
                    acch[j][c] = __hfma2(m1, t1, acch[j][c]);
                    acch[j][c] = __hfma2(m2, t2, acch[j][c]);
                }
            }
            iv = ivn; ov = ovn;
        }

        #pragma unroll
        for (int j = 0; j < 2; j++)
            #pragma unroll
            for (int c = 0; c < 2; c++) {
                accf[j][c][0] += __low2float(acch[j][c]);
                accf[j][c][1] += __high2float(acch[j][c]);
            }
        __syncthreads();
    }

    // epilogue: lanes along i -> 128B coalesced stores
    #pragma unroll
    for (int j = 0; j < 2; j++) {
        const int i = iBase + j * 32 + tx;
        #pragma unroll
        for (int c = 0; c < 2; c++) {
            #pragma unroll
            for (int h = 0; h < 2; h++) {
                int o = oBase + wp * 4 + c * 2 + h;
                size_t off = (size_t)o * IN_ + i;
                outW[off] = W[off] + accf[j][c][h] * A_SC;
            }
        }
    }
}

// ---------------------------------------------------------------------------
extern "C" void kernel_launch(void* const* d_in, const int* in_sizes, int n_in,
                              void* d_out, int out_size)
{
    const float* spikes   = (const float*)d_in[0];
    const float* W        = (const float*)d_in[1];
    const float* membrane = (const float*)d_in[2];
    const float* dpre     = (const float*)d_in[3];
    const float* dfire    = (const float*)d_in[4];

    float* out       = (float*)d_out;
    float* out_spike = out;                                   // (B, OUT)
    float* out_W     = out + B_ * OUT_;                       // (OUT, IN)
    float* out_mem   = out + B_ * OUT_ + (size_t)OUT_ * IN_;  // (B, OUT)

    k_front<<<1664, 256>>>(W, spikes, dpre);
    k_mm_lif<<<dim3(2, 128), 256>>>(membrane, dfire, out_spike, out_mem);
    k_stdp<<<dim3(64, 16), 128>>>(W, out_W);
}